// round 1
// baseline (speedup 1.0000x reference)
#include <cuda_runtime.h>
#include <math.h>

#define NPTS 8192
#define DIMS 128
#define TILE 128
#define NB   (NPTS / TILE)   // 64
#define LDA  132             // padded stride for transposed smem tiles

// ---------------- global scratch (no allocations allowed) ----------------
__device__ float  g_norm_x[NPTS];
__device__ float  g_norm_y[NPTS];
__device__ double g_rs_a[NPTS];   // row sums of distance matrix A (x)
__device__ double g_rs_b[NPTS];   // row sums of distance matrix B (y)
__device__ double g_S[3];         // [0]=Sum d_x^2, [1]=Sum d_y^2, [2]=Sum d_x*d_y

// ---------------- kernel 1: zero scratch + squared norms ----------------
__global__ void init_norms_kernel(const float* __restrict__ x,
                                  const float* __restrict__ y) {
    int i = blockIdx.x * blockDim.x + threadIdx.x;
    if (i < 3) g_S[i] = 0.0;
    if (i >= NPTS) return;
    g_rs_a[i] = 0.0;
    g_rs_b[i] = 0.0;
    const float4* xr = reinterpret_cast<const float4*>(x) + i * (DIMS / 4);
    const float4* yr = reinterpret_cast<const float4*>(y) + i * (DIMS / 4);
    float sx = 0.f, sy = 0.f;
#pragma unroll
    for (int k = 0; k < DIMS / 4; k++) {
        float4 v = xr[k];
        sx = fmaf(v.x, v.x, sx); sx = fmaf(v.y, v.y, sx);
        sx = fmaf(v.z, v.z, sx); sx = fmaf(v.w, v.w, sx);
        float4 w = yr[k];
        sy = fmaf(w.x, w.x, sy); sy = fmaf(w.y, w.y, sy);
        sy = fmaf(w.z, w.z, sy); sy = fmaf(w.w, w.w, sy);
    }
    g_norm_x[i] = sx;
    g_norm_y[i] = sy;
}

// Load a 128-row x 128-col fp32 tile, transposed (K-major) into smem [k][row].
__device__ __forceinline__ void load_tile_T(const float* __restrict__ p, int rowBase,
                                            float* __restrict__ dst, int tid) {
    const float4* src = reinterpret_cast<const float4*>(p + (size_t)rowBase * DIMS);
#pragma unroll
    for (int it = 0; it < 16; it++) {                 // 4096 float4 / 256 threads
        int t  = tid + it * 256;
        int r  = t >> 5;                              // row within tile
        int k4 = t & 31;                              // float4 index within row
        float4 v = src[r * (DIMS / 4) + k4];
        int kk = k4 << 2;
        dst[(kk + 0) * LDA + r] = v.x;
        dst[(kk + 1) * LDA + r] = v.y;
        dst[(kk + 2) * LDA + r] = v.z;
        dst[(kk + 3) * LDA + r] = v.w;
    }
}

// 128x128x128 fp32 Gram block: acc[r][c] = sum_k A[i0+r][k] * B[j0+c][k]
__device__ __forceinline__ void gram128(const float* __restrict__ smA,
                                        const float* __restrict__ smB,
                                        int i0, int j0, float acc[8][8]) {
#pragma unroll
    for (int r = 0; r < 8; r++)
#pragma unroll
        for (int c = 0; c < 8; c++) acc[r][c] = 0.f;
#pragma unroll 4
    for (int kk = 0; kk < DIMS; kk++) {
        float a[8], b[8];
        *reinterpret_cast<float4*>(&a[0]) = *reinterpret_cast<const float4*>(&smA[kk * LDA + i0]);
        *reinterpret_cast<float4*>(&a[4]) = *reinterpret_cast<const float4*>(&smA[kk * LDA + i0 + 4]);
        *reinterpret_cast<float4*>(&b[0]) = *reinterpret_cast<const float4*>(&smB[kk * LDA + j0]);
        *reinterpret_cast<float4*>(&b[4]) = *reinterpret_cast<const float4*>(&smB[kk * LDA + j0 + 4]);
#pragma unroll
        for (int r = 0; r < 8; r++)
#pragma unroll
            for (int c = 0; c < 8; c++)
                acc[r][c] = fmaf(a[r], b[c], acc[r][c]);
    }
}

// ---------------- kernel 2: tile sweep (upper triangle) ----------------
__global__ __launch_bounds__(256, 1)
void dcor_tiles_kernel(const float* __restrict__ x, const float* __restrict__ y) {
    const int bi = blockIdx.y, bj = blockIdx.x;
    if (bj < bi) return;

    extern __shared__ float sm[];
    float* smA   = sm;                                  // [128][LDA] transposed tile
    float* smB   = sm + TILE * LDA;
    float* dT    = sm + 2 * TILE * LDA;                 // d_x tile [128][128]
    float* rowb  = dT + TILE * TILE;                    // [128] row sums
    float* colb2 = rowb + TILE;                         // [16][128] per-ty col partials
    __shared__ double redS[3][8];

    const int tid = threadIdx.x;
    const int tx = tid & 15, ty = tid >> 4;
    const int i0 = ty * 8, j0 = tx * 8;
    const int I = bi * TILE, J = bj * TILE;
    const bool diag = (bi == bj);
    const unsigned FULL = 0xffffffffu;

    float acc[8][8];
    double s_aa = 0.0, s_bb = 0.0, s_ab = 0.0;

    // ================= stage X =================
    load_tile_T(x, I, smA, tid);
    load_tile_T(x, J, smB, tid);
    __syncthreads();
    gram128(smA, smB, i0, j0, acc);
    {
        float nI[8], nJ[8];
#pragma unroll
        for (int r = 0; r < 8; r++) nI[r] = g_norm_x[I + i0 + r];
#pragma unroll
        for (int c = 0; c < 8; c++) nJ[c] = g_norm_x[J + j0 + c];
        float colp[8] = {0, 0, 0, 0, 0, 0, 0, 0};
#pragma unroll
        for (int r = 0; r < 8; r++) {
            float rowp = 0.f, rsq = 0.f;
#pragma unroll
            for (int c = 0; c < 8; c++) {
                float sq = fmaf(-2.f, acc[r][c], nI[r] + nJ[c]);
                float dv = (sq > 0.f) ? sq * rsqrtf(sq) : 0.f;
                if (diag && (i0 + r) == (j0 + c)) dv = 0.f;   // exact-zero diagonal
                dT[(i0 + r) * TILE + (j0 + c)] = dv;
                rowp = rowp + dv;
                colp[c] = colp[c] + dv;
                rsq = fmaf(dv, dv, rsq);
            }
            s_aa += (double)rsq;
            // reduce rowp across tx (lanes 0..15 / 16..31 of the warp)
            rowp += __shfl_xor_sync(FULL, rowp, 1);
            rowp += __shfl_xor_sync(FULL, rowp, 2);
            rowp += __shfl_xor_sync(FULL, rowp, 4);
            rowp += __shfl_xor_sync(FULL, rowp, 8);
            if (tx == 0) rowb[i0 + r] = rowp;
        }
#pragma unroll
        for (int c = 0; c < 8; c++) colb2[ty * TILE + j0 + c] = colp[c];
    }
    __syncthreads();   // (A) dT, rowb, colb2 complete; smA/smB free
    if (tid < TILE) {
        float cs = 0.f;
#pragma unroll
        for (int t = 0; t < 16; t++) cs += colb2[t * TILE + tid];
        atomicAdd(&g_rs_a[I + tid], (double)rowb[tid]);
        if (!diag) atomicAdd(&g_rs_a[J + tid], (double)cs);
    }

    // ================= stage Y =================
    load_tile_T(y, I, smA, tid);
    load_tile_T(y, J, smB, tid);
    __syncthreads();   // (B)
    gram128(smA, smB, i0, j0, acc);
    {
        float nI[8], nJ[8];
#pragma unroll
        for (int r = 0; r < 8; r++) nI[r] = g_norm_y[I + i0 + r];
#pragma unroll
        for (int c = 0; c < 8; c++) nJ[c] = g_norm_y[J + j0 + c];
        float colp[8] = {0, 0, 0, 0, 0, 0, 0, 0};
#pragma unroll
        for (int r = 0; r < 8; r++) {
            float rowp = 0.f, rsq = 0.f, rab = 0.f;
#pragma unroll
            for (int c = 0; c < 8; c++) {
                float sq = fmaf(-2.f, acc[r][c], nI[r] + nJ[c]);
                float dv = (sq > 0.f) ? sq * rsqrtf(sq) : 0.f;
                if (diag && (i0 + r) == (j0 + c)) dv = 0.f;
                float dxv = dT[(i0 + r) * TILE + (j0 + c)];
                rowp = rowp + dv;
                colp[c] = colp[c] + dv;
                rsq = fmaf(dv, dv, rsq);
                rab = fmaf(dxv, dv, rab);
            }
            s_bb += (double)rsq;
            s_ab += (double)rab;
            rowp += __shfl_xor_sync(FULL, rowp, 1);
            rowp += __shfl_xor_sync(FULL, rowp, 2);
            rowp += __shfl_xor_sync(FULL, rowp, 4);
            rowp += __shfl_xor_sync(FULL, rowp, 8);
            if (tx == 0) rowb[i0 + r] = rowp;
        }
#pragma unroll
        for (int c = 0; c < 8; c++) colb2[ty * TILE + j0 + c] = colp[c];
    }
    __syncthreads();
    if (tid < TILE) {
        float cs = 0.f;
#pragma unroll
        for (int t = 0; t < 16; t++) cs += colb2[t * TILE + tid];
        atomicAdd(&g_rs_b[I + tid], (double)rowb[tid]);
        if (!diag) atomicAdd(&g_rs_b[J + tid], (double)cs);
    }

    // ---- block-level scalar reduction (double) ----
    const double w = diag ? 1.0 : 2.0;
    s_aa *= w; s_bb *= w; s_ab *= w;
#pragma unroll
    for (int o = 16; o; o >>= 1) {
        s_aa += __shfl_down_sync(FULL, s_aa, o);
        s_bb += __shfl_down_sync(FULL, s_bb, o);
        s_ab += __shfl_down_sync(FULL, s_ab, o);
    }
    int wid = tid >> 5, lane = tid & 31;
    if (lane == 0) { redS[0][wid] = s_aa; redS[1][wid] = s_bb; redS[2][wid] = s_ab; }
    __syncthreads();
    if (tid == 0) {
        double a = 0, b = 0, c = 0;
#pragma unroll
        for (int k = 0; k < 8; k++) { a += redS[0][k]; b += redS[1][k]; c += redS[2][k]; }
        atomicAdd(&g_S[0], a);
        atomicAdd(&g_S[1], b);
        atomicAdd(&g_S[2], c);
    }
}

// ---------------- kernel 3: combine + final scalar ----------------
__global__ void finalize_kernel(float* __restrict__ out) {
    int tid = threadIdx.x;
    double dAB = 0, dAA = 0, dBB = 0, Ta = 0, Tb = 0;
    for (int i = tid; i < NPTS; i += 256) {
        double a = g_rs_a[i], b = g_rs_b[i];
        dAB += a * b; dAA += a * a; dBB += b * b; Ta += a; Tb += b;
    }
    const unsigned FULL = 0xffffffffu;
#pragma unroll
    for (int o = 16; o; o >>= 1) {
        dAB += __shfl_down_sync(FULL, dAB, o);
        dAA += __shfl_down_sync(FULL, dAA, o);
        dBB += __shfl_down_sync(FULL, dBB, o);
        Ta  += __shfl_down_sync(FULL, Ta,  o);
        Tb  += __shfl_down_sync(FULL, Tb,  o);
    }
    __shared__ double red[5][8];
    int wid = tid >> 5, lane = tid & 31;
    if (lane == 0) {
        red[0][wid] = dAB; red[1][wid] = dAA; red[2][wid] = dBB;
        red[3][wid] = Ta;  red[4][wid] = Tb;
    }
    __syncthreads();
    if (tid == 0) {
        double sAB = 0, sAA = 0, sBB = 0, ta = 0, tb = 0;
#pragma unroll
        for (int k = 0; k < 8; k++) {
            sAB += red[0][k]; sAA += red[1][k]; sBB += red[2][k];
            ta  += red[3][k]; tb  += red[4][k];
        }
        const double n = (double)NPTS;
        const double inv_n2 = 1.0 / (n * n);
        // Sum(A o B) = Sum(a b) - (2/n) Sum_i rs_a rs_b + Ta Tb / n^2
        double xy = (g_S[2] - (2.0 / n) * sAB + ta * tb * inv_n2) * inv_n2;
        double xx = (g_S[0] - (2.0 / n) * sAA + ta * ta * inv_n2) * inv_n2;
        double yy = (g_S[1] - (2.0 / n) * sBB + tb * tb * inv_n2) * inv_n2;
        xy = fmax(xy, 0.0); xx = fmax(xx, 0.0); yy = fmax(yy, 0.0);
        double dcor = -sqrt(xy) / sqrt(sqrt(xx) * sqrt(yy));
        out[0] = (float)dcor;
    }
}

extern "C" void kernel_launch(void* const* d_in, const int* in_sizes, int n_in,
                              void* d_out, int out_size) {
    (void)in_sizes; (void)n_in; (void)out_size;
    const float* x = (const float*)d_in[0];
    const float* y = (const float*)d_in[1];
    float* out = (float*)d_out;

    constexpr size_t SMEM =
        (size_t)(2 * TILE * LDA + TILE * TILE + TILE + 16 * TILE) * sizeof(float);
    cudaFuncSetAttribute(dcor_tiles_kernel,
                         cudaFuncAttributeMaxDynamicSharedMemorySize, (int)SMEM);

    init_norms_kernel<<<(NPTS + 255) / 256, 256>>>(x, y);
    dim3 grid(NB, NB);
    dcor_tiles_kernel<<<grid, 256, SMEM>>>(x, y);
    finalize_kernel<<<1, 256>>>(out);
}

// round 3
// speedup vs baseline: 1.7003x; 1.7003x over previous
#include <cuda_runtime.h>
#include <math.h>
#include <stdint.h>

#define NPTS 8192
#define DIMS 128
#define TILE 128
#define NB   (NPTS / TILE)   // 64

// smem layout in floats (padded stride 68: 68 % 32 == 4 -> conflict-free frags)
#define OPLEN     (128 * 68)          // 8704 floats per operand buffer
#define OFF_AH    0
#define OFF_AL    (OFF_AH + OPLEN)
#define OFF_BH    (OFF_AL + OPLEN)
#define OFF_BL    (OFF_BH + OPLEN)
#define OFF_DT    (OFF_BL + OPLEN)    // 34816
#define DT_LD     132
#define OFF_NI    (OFF_DT + 128 * DT_LD)   // 51712
#define OFF_NJ    (OFF_NI + 128)
#define OFF_RB    (OFF_NJ + 128)           // 256 floats
#define SMEM_FLOATS (OFF_RB + 256)         // 52224
#define SMEM_BYTES  (SMEM_FLOATS * 4)      // 208896

// ---------------- global scratch ----------------
__device__ float  g_norm_x[NPTS];
__device__ float  g_norm_y[NPTS];
__device__ double g_rs_a[NPTS];
__device__ double g_rs_b[NPTS];
__device__ double g_S[3];   // [0]=Sum dx^2, [1]=Sum dy^2, [2]=Sum dx*dy

// ---------------- kernel 1: zero scratch + squared norms ----------------
__global__ void init_norms_kernel(const float* __restrict__ x,
                                  const float* __restrict__ y) {
    int i = blockIdx.x * blockDim.x + threadIdx.x;
    if (i < 3) g_S[i] = 0.0;
    if (i >= NPTS) return;
    g_rs_a[i] = 0.0;
    g_rs_b[i] = 0.0;
    const float4* xr = reinterpret_cast<const float4*>(x) + i * (DIMS / 4);
    const float4* yr = reinterpret_cast<const float4*>(y) + i * (DIMS / 4);
    float sx = 0.f, sy = 0.f;
#pragma unroll
    for (int k = 0; k < DIMS / 4; k++) {
        float4 v = xr[k];
        sx = fmaf(v.x, v.x, sx); sx = fmaf(v.y, v.y, sx);
        sx = fmaf(v.z, v.z, sx); sx = fmaf(v.w, v.w, sx);
        float4 w = yr[k];
        sy = fmaf(w.x, w.x, sy); sy = fmaf(w.y, w.y, sy);
        sy = fmaf(w.z, w.z, sy); sy = fmaf(w.w, w.w, sy);
    }
    g_norm_x[i] = sx;
    g_norm_y[i] = sy;
}

// ---------------- helpers ----------------
__device__ __forceinline__ void mma_tf32(float* d,
                                         uint32_t a0, uint32_t a1, uint32_t a2, uint32_t a3,
                                         uint32_t b0, uint32_t b1) {
    asm volatile(
        "mma.sync.aligned.m16n8k8.row.col.f32.tf32.tf32.f32 "
        "{%0,%1,%2,%3}, {%4,%5,%6,%7}, {%8,%9}, {%0,%1,%2,%3};"
        : "+f"(d[0]), "+f"(d[1]), "+f"(d[2]), "+f"(d[3])
        : "r"(a0), "r"(a1), "r"(a2), "r"(a3), "r"(b0), "r"(b1));
}

__device__ __forceinline__ void split_tf32(float v, float& hi, float& lo) {
    hi = __uint_as_float(__float_as_uint(v) & 0xffffe000u);
    float l = v - hi;                       // exact
    lo = __uint_as_float(__float_as_uint(l) & 0xffffe000u);
}

// Load 128 rows x 64 k-cols slice from gmem, split hi/lo, store row-major [128][68].
__device__ __forceinline__ void load_conv(const float* __restrict__ src, int rowBase, int kc,
                                          float* __restrict__ hb, float* __restrict__ lb,
                                          int tid) {
    const float4* s4 = reinterpret_cast<const float4*>(src + (size_t)rowBase * DIMS + kc);
#pragma unroll
    for (int i = 0; i < 8; i++) {           // 128 rows * 16 float4 / 256 threads
        int t  = tid + i * 256;
        int r  = t >> 4;
        int k4 = t & 15;
        float4 v = s4[r * (DIMS / 4) + k4];
        float4 h, l;
        split_tf32(v.x, h.x, l.x); split_tf32(v.y, h.y, l.y);
        split_tf32(v.z, h.z, l.z); split_tf32(v.w, h.w, l.w);
        int o = r * 68 + k4 * 4;
        *reinterpret_cast<float4*>(hb + o) = h;
        *reinterpret_cast<float4*>(lb + o) = l;
    }
}

// ---------------- kernel 2: HMMA tile sweep (upper triangle) ----------------
__global__ __launch_bounds__(256, 1)
void dcor_mma_kernel(const float* __restrict__ x, const float* __restrict__ y) {
    const int bi = blockIdx.y, bj = blockIdx.x;
    if (bj < bi) return;

    extern __shared__ float sm[];
    float* AH = sm + OFF_AH;
    float* AL = sm + OFF_AL;
    float* BH = sm + OFF_BH;
    float* BL = sm + OFF_BL;
    float* dT = sm + OFF_DT;
    float* NI = sm + OFF_NI;
    float* NJ = sm + OFF_NJ;
    float* RB = sm + OFF_RB;

    const int tid = threadIdx.x, warp = tid >> 5, lane = tid & 31;
    const bool diag = (bi == bj);
    const int I = bi * TILE, J = bj * TILE;
    const int mwarp = warp & 3;      // row quarter: rows [mwarp*32, +32)
    const int nhalf = warp >> 2;     // col half:   cols [nhalf*64, +64)
    const unsigned FULL = 0xffffffffu;

    const uint32_t* AHu = reinterpret_cast<const uint32_t*>(AH);
    const uint32_t* ALu = reinterpret_cast<const uint32_t*>(AL);
    const uint32_t* BHu = reinterpret_cast<const uint32_t*>(BH);
    const uint32_t* BLu = reinterpret_cast<const uint32_t*>(BL);

    double s_aa = 0.0, s_bb = 0.0, s_ab = 0.0;

#pragma unroll
    for (int g = 0; g < 2; g++) {
        const float* src = g ? y : x;
        const float* nrm = g ? g_norm_y : g_norm_x;
        double* grs = g ? g_rs_b : g_rs_a;

        float acc[2][8][4];
#pragma unroll
        for (int mt = 0; mt < 2; mt++)
#pragma unroll
            for (int nt = 0; nt < 8; nt++)
#pragma unroll
                for (int q = 0; q < 4; q++) acc[mt][nt][q] = 0.f;

#pragma unroll
        for (int chunk = 0; chunk < 2; chunk++) {
            const int kc = chunk * 64;
            load_conv(src, I, kc, AH, AL, tid);
            load_conv(src, J, kc, BH, BL, tid);
            if (chunk == 0 && tid < 128) { NI[tid] = nrm[I + tid]; NJ[tid] = nrm[J + tid]; }
            __syncthreads();

#pragma unroll
            for (int ks = 0; ks < 8; ks++) {
                const int k0 = ks * 8 + (lane & 3);
                uint32_t ah[2][4], al[2][4];
#pragma unroll
                for (int mt = 0; mt < 2; mt++) {
                    const int ar = mwarp * 32 + mt * 16 + (lane >> 2);
                    ah[mt][0] = AHu[ar * 68 + k0];
                    ah[mt][1] = AHu[(ar + 8) * 68 + k0];
                    ah[mt][2] = AHu[ar * 68 + k0 + 4];
                    ah[mt][3] = AHu[(ar + 8) * 68 + k0 + 4];
                    al[mt][0] = ALu[ar * 68 + k0];
                    al[mt][1] = ALu[(ar + 8) * 68 + k0];
                    al[mt][2] = ALu[ar * 68 + k0 + 4];
                    al[mt][3] = ALu[(ar + 8) * 68 + k0 + 4];
                }
#pragma unroll
                for (int nt = 0; nt < 8; nt++) {
                    const int bn = nhalf * 64 + nt * 8 + (lane >> 2);
                    uint32_t bh0 = BHu[bn * 68 + k0];
                    uint32_t bh1 = BHu[bn * 68 + k0 + 4];
                    uint32_t bl0 = BLu[bn * 68 + k0];
                    uint32_t bl1 = BLu[bn * 68 + k0 + 4];
#pragma unroll
                    for (int mt = 0; mt < 2; mt++) {
                        mma_tf32(acc[mt][nt], ah[mt][0], ah[mt][1], ah[mt][2], ah[mt][3], bh0, bh1);
                        mma_tf32(acc[mt][nt], ah[mt][0], ah[mt][1], ah[mt][2], ah[mt][3], bl0, bl1);
                        mma_tf32(acc[mt][nt], al[mt][0], al[mt][1], al[mt][2], al[mt][3], bh0, bh1);
                    }
                }
            }
            __syncthreads();   // operands free before next chunk / stage
        }

        // ---- epilogue: distances from accumulators, write dT, local sums ----
        float ssq = 0.f, sab = 0.f;
#pragma unroll
        for (int mt = 0; mt < 2; mt++) {
#pragma unroll
            for (int pr = 0; pr < 2; pr++) {
                const int row = mwarp * 32 + mt * 16 + (lane >> 2) + pr * 8;
                const float nIr = NI[row];
#pragma unroll
                for (int nt = 0; nt < 8; nt++) {
                    const int col = nhalf * 64 + nt * 8 + (lane & 3) * 2;
                    float g0 = acc[mt][nt][pr * 2 + 0];
                    float g1 = acc[mt][nt][pr * 2 + 1];
                    float sq0 = fmaf(-2.f, g0, nIr + NJ[col]);
                    float sq1 = fmaf(-2.f, g1, nIr + NJ[col + 1]);
                    float dv0 = (sq0 > 0.f) ? sq0 * rsqrtf(sq0) : 0.f;
                    float dv1 = (sq1 > 0.f) ? sq1 * rsqrtf(sq1) : 0.f;
                    if (diag) {
                        if (row == col)     dv0 = 0.f;
                        if (row == col + 1) dv1 = 0.f;
                    }
                    float* dst = &dT[row * DT_LD + col];
                    if (g == 1) {
                        float2 dx = *reinterpret_cast<const float2*>(dst);
                        sab = fmaf(dx.x, dv0, sab);
                        sab = fmaf(dx.y, dv1, sab);
                    }
                    float2 o; o.x = dv0; o.y = dv1;
                    *reinterpret_cast<float2*>(dst) = o;
                    ssq = fmaf(dv0, dv0, ssq);
                    ssq = fmaf(dv1, dv1, ssq);
                }
            }
        }
        if (g == 0) { s_aa += (double)ssq; }
        else        { s_bb += (double)ssq; s_ab += (double)sab; }
        __syncthreads();   // dT complete

        // ---- sum phase: row + col sums from dT ----
        {
            const int row = tid >> 1, h = tid & 1;
            float rp = 0.f;
            const float* p = &dT[row * DT_LD + h * 64];
#pragma unroll 16
            for (int c = 0; c < 64; c++) rp += p[c];
            RB[tid] = rp;
        }
        __syncthreads();
        if (tid < 128) {
            float cs = 0.f;
#pragma unroll 8
            for (int r = 0; r < 128; r++) cs += dT[r * DT_LD + tid];
            double rs = (double)RB[2 * tid] + (double)RB[2 * tid + 1];
            atomicAdd(&grs[I + tid], rs);
            if (!diag) atomicAdd(&grs[J + tid], (double)cs);
        }
        __syncthreads();   // dT free for next stage
    }

    // ---- block scalar reduction ----
    const double w = diag ? 1.0 : 2.0;
    s_aa *= w; s_bb *= w; s_ab *= w;
#pragma unroll
    for (int o = 16; o; o >>= 1) {
        s_aa += __shfl_down_sync(FULL, s_aa, o);
        s_bb += __shfl_down_sync(FULL, s_bb, o);
        s_ab += __shfl_down_sync(FULL, s_ab, o);
    }
    __shared__ double redS[3][8];
    if (lane == 0) { redS[0][warp] = s_aa; redS[1][warp] = s_bb; redS[2][warp] = s_ab; }
    __syncthreads();
    if (tid == 0) {
        double a = 0, b = 0, c = 0;
#pragma unroll
        for (int k = 0; k < 8; k++) { a += redS[0][k]; b += redS[1][k]; c += redS[2][k]; }
        atomicAdd(&g_S[0], a);
        atomicAdd(&g_S[1], b);
        atomicAdd(&g_S[2], c);
    }
}

// ---------------- kernel 3: combine + final scalar ----------------
__global__ void finalize_kernel(float* __restrict__ out) {
    int tid = threadIdx.x;
    double dAB = 0, dAA = 0, dBB = 0, Ta = 0, Tb = 0;
    for (int i = tid; i < NPTS; i += 256) {
        double a = g_rs_a[i], b = g_rs_b[i];
        dAB += a * b; dAA += a * a; dBB += b * b; Ta += a; Tb += b;
    }
    const unsigned FULL = 0xffffffffu;
#pragma unroll
    for (int o = 16; o; o >>= 1) {
        dAB += __shfl_down_sync(FULL, dAB, o);
        dAA += __shfl_down_sync(FULL, dAA, o);
        dBB += __shfl_down_sync(FULL, dBB, o);
        Ta  += __shfl_down_sync(FULL, Ta,  o);
        Tb  += __shfl_down_sync(FULL, Tb,  o);
    }
    __shared__ double red[5][8];
    int wid = tid >> 5, lane = tid & 31;
    if (lane == 0) {
        red[0][wid] = dAB; red[1][wid] = dAA; red[2][wid] = dBB;
        red[3][wid] = Ta;  red[4][wid] = Tb;
    }
    __syncthreads();
    if (tid == 0) {
        double sAB = 0, sAA = 0, sBB = 0, ta = 0, tb = 0;
#pragma unroll
        for (int k = 0; k < 8; k++) {
            sAB += red[0][k]; sAA += red[1][k]; sBB += red[2][k];
            ta  += red[3][k]; tb  += red[4][k];
        }
        const double n = (double)NPTS;
        const double inv_n2 = 1.0 / (n * n);
        double xy = (g_S[2] - (2.0 / n) * sAB + ta * tb * inv_n2) * inv_n2;
        double xx = (g_S[0] - (2.0 / n) * sAA + ta * ta * inv_n2) * inv_n2;
        double yy = (g_S[1] - (2.0 / n) * sBB + tb * tb * inv_n2) * inv_n2;
        xy = fmax(xy, 0.0); xx = fmax(xx, 0.0); yy = fmax(yy, 0.0);
        double dcor = -sqrt(xy) / sqrt(sqrt(xx) * sqrt(yy));
        out[0] = (float)dcor;
    }
}

extern "C" void kernel_launch(void* const* d_in, const int* in_sizes, int n_in,
                              void* d_out, int out_size) {
    (void)in_sizes; (void)n_in; (void)out_size;
    const float* x = (const float*)d_in[0];
    const float* y = (const float*)d_in[1];
    float* out = (float*)d_out;

    cudaFuncSetAttribute(dcor_mma_kernel,
                         cudaFuncAttributeMaxDynamicSharedMemorySize, SMEM_BYTES);

    init_norms_kernel<<<(NPTS + 255) / 256, 256>>>(x, y);
    dim3 grid(NB, NB);
    dcor_mma_kernel<<<grid, 256, SMEM_BYTES>>>(x, y);
    finalize_kernel<<<1, 256>>>(out);
}

// round 6
// speedup vs baseline: 1.8291x; 1.0757x over previous
#include <cuda_runtime.h>
#include <math.h>
#include <stdint.h>

#define NPTS 8192
#define DIMS 128
#define TILE 128
#define NB   (NPTS / TILE)   // 64

// ---- smem layout (floats) ----
// double-buffered 32-k chunk operands: [2 bufs][4 arrays][128 rows][36] (32 k + 4 pad)
#define ROW_STRIDE 36
#define ARR_STRIDE (128 * ROW_STRIDE)  // 4608
#define BUF_STRIDE (4 * ARR_STRIDE)    // 18432
#define OFF_DT     (2 * BUF_STRIDE)    // 36864
#define DT_LD      132
#define OFF_NI     (OFF_DT + 128 * DT_LD)  // 53760
#define OFF_NJ     (OFF_NI + 128)
#define OFF_COLP   (OFF_NJ + 128)          // [4][128]
#define OFF_ROWP   (OFF_COLP + 512)        // [2][128]
#define SMEM_FLOATS (OFF_ROWP + 256)       // 54784
#define SMEM_BYTES  (SMEM_FLOATS * 4)      // 219136

// ---- global scratch (16B aligned for cp.async) ----
__device__ __align__(16) float g_xh[NPTS * DIMS];
__device__ __align__(16) float g_xl[NPTS * DIMS];
__device__ __align__(16) float g_yh[NPTS * DIMS];
__device__ __align__(16) float g_yl[NPTS * DIMS];
__device__ float  g_norm_x[NPTS];
__device__ float  g_norm_y[NPTS];
__device__ double g_rs_a[NPTS];
__device__ double g_rs_b[NPTS];
__device__ double g_S[3];   // [0]=Sum dx^2, [1]=Sum dy^2, [2]=Sum dx*dy

// ---- helpers ----
__device__ __forceinline__ void mma_tf32(float* d,
                                         uint32_t a0, uint32_t a1, uint32_t a2, uint32_t a3,
                                         uint32_t b0, uint32_t b1) {
    asm volatile(
        "mma.sync.aligned.m16n8k8.row.col.f32.tf32.tf32.f32 "
        "{%0,%1,%2,%3}, {%4,%5,%6,%7}, {%8,%9}, {%0,%1,%2,%3};"
        : "+f"(d[0]), "+f"(d[1]), "+f"(d[2]), "+f"(d[3])
        : "r"(a0), "r"(a1), "r"(a2), "r"(a3), "r"(b0), "r"(b1));
}

__device__ __forceinline__ uint32_t smem_u32(const void* p) {
    uint32_t a;
    asm("{ .reg .u64 t; cvta.to.shared.u64 t, %1; cvt.u32.u64 %0, t; }" : "=r"(a) : "l"(p));
    return a;
}
__device__ __forceinline__ void cpa16(uint32_t dst, const float* src) {
    asm volatile("cp.async.ca.shared.global [%0], [%1], 16;" :: "r"(dst), "l"(src));
}
#define CP_COMMIT() asm volatile("cp.async.commit_group;" ::: "memory")
#define CP_WAIT(N)  asm volatile("cp.async.wait_group %0;" :: "n"(N) : "memory")

__device__ __forceinline__ void split_tf32(float v, float& hi, float& lo) {
    hi = __uint_as_float(__float_as_uint(v) & 0xffffe000u);
    float l = v - hi;
    lo = __uint_as_float(__float_as_uint(l) & 0xffffe000u);
}

// ---- kernel 1: pre-split x/y into tf32 hi/lo + norms + zero scratch ----
__global__ __launch_bounds__(256, 4)
void prep_kernel(const float* __restrict__ x, const float* __restrict__ y) {
    const int warp = threadIdx.x >> 5, lane = threadIdx.x & 31;
    const int r = blockIdx.x * 8 + warp;
    if (blockIdx.x == 0 && threadIdx.x < 3) g_S[threadIdx.x] = 0.0;

    const float4 vx = reinterpret_cast<const float4*>(x + (size_t)r * DIMS)[lane];
    const float4 vy = reinterpret_cast<const float4*>(y + (size_t)r * DIMS)[lane];
    float4 h, l;
    split_tf32(vx.x, h.x, l.x); split_tf32(vx.y, h.y, l.y);
    split_tf32(vx.z, h.z, l.z); split_tf32(vx.w, h.w, l.w);
    reinterpret_cast<float4*>(g_xh + (size_t)r * DIMS)[lane] = h;
    reinterpret_cast<float4*>(g_xl + (size_t)r * DIMS)[lane] = l;
    float sx = vx.x * vx.x + vx.y * vx.y + vx.z * vx.z + vx.w * vx.w;

    split_tf32(vy.x, h.x, l.x); split_tf32(vy.y, h.y, l.y);
    split_tf32(vy.z, h.z, l.z); split_tf32(vy.w, h.w, l.w);
    reinterpret_cast<float4*>(g_yh + (size_t)r * DIMS)[lane] = h;
    reinterpret_cast<float4*>(g_yl + (size_t)r * DIMS)[lane] = l;
    float sy = vy.x * vy.x + vy.y * vy.y + vy.z * vy.z + vy.w * vy.w;

    const unsigned FULL = 0xffffffffu;
#pragma unroll
    for (int o = 16; o; o >>= 1) {
        sx += __shfl_xor_sync(FULL, sx, o);
        sy += __shfl_xor_sync(FULL, sy, o);
    }
    if (lane == 0) {
        g_norm_x[r] = sx; g_norm_y[r] = sy;
        g_rs_a[r] = 0.0;  g_rs_b[r] = 0.0;
    }
}

// issue cp.async for one 32-k chunk into buffer `buf` (4 arrays: AH, AL, BH, BL)
__device__ __forceinline__ void issue_chunk(uint32_t smb, int buf,
                                            const float* __restrict__ srch,
                                            const float* __restrict__ srcl,
                                            int I, int J, int kc, int tid) {
    const uint32_t base = smb + (uint32_t)(buf * BUF_STRIDE) * 4u;
#pragma unroll
    for (int i = 0; i < 4; i++) {           // 128 rows * 8 float4 / 256 threads
        const int t  = tid + i * 256;
        const int r  = t >> 3;              // row 0..127
        const int k4 = t & 7;               // float4 0..7 (k = k4*4, 32 floats)
        const uint32_t d = base + (uint32_t)(r * ROW_STRIDE + k4 * 4) * 4u;
        const int so = r * DIMS + kc + k4 * 4;
        cpa16(d,                        srch + (size_t)I * DIMS + so);
        cpa16(d + ARR_STRIDE * 4u,      srcl + (size_t)I * DIMS + so);
        cpa16(d + 2u * ARR_STRIDE * 4u, srch + (size_t)J * DIMS + so);
        cpa16(d + 3u * ARR_STRIDE * 4u, srcl + (size_t)J * DIMS + so);
    }
    CP_COMMIT();
}

// run 4 k-steps (32 k) of MMA over one buffer
__device__ __forceinline__ void mma_buffer(const float* __restrict__ sm, int buf,
                                           float acc[2][8][4], int mwarp, int nhalf, int lane) {
    const uint32_t* AHu = reinterpret_cast<const uint32_t*>(sm + buf * BUF_STRIDE);
    const uint32_t* ALu = AHu + ARR_STRIDE;
    const uint32_t* BHu = AHu + 2 * ARR_STRIDE;
    const uint32_t* BLu = AHu + 3 * ARR_STRIDE;
#pragma unroll
    for (int ks = 0; ks < 4; ks++) {
        const int k0 = ks * 8 + (lane & 3);
        uint32_t ah[2][4], al[2][4];
#pragma unroll
        for (int mt = 0; mt < 2; mt++) {
            const int ar = mwarp * 32 + mt * 16 + (lane >> 2);
            ah[mt][0] = AHu[ar * ROW_STRIDE + k0];
            ah[mt][1] = AHu[(ar + 8) * ROW_STRIDE + k0];
            ah[mt][2] = AHu[ar * ROW_STRIDE + k0 + 4];
            ah[mt][3] = AHu[(ar + 8) * ROW_STRIDE + k0 + 4];
            al[mt][0] = ALu[ar * ROW_STRIDE + k0];
            al[mt][1] = ALu[(ar + 8) * ROW_STRIDE + k0];
            al[mt][2] = ALu[ar * ROW_STRIDE + k0 + 4];
            al[mt][3] = ALu[(ar + 8) * ROW_STRIDE + k0 + 4];
        }
#pragma unroll
        for (int nt = 0; nt < 8; nt++) {
            const int bn = nhalf * 64 + nt * 8 + (lane >> 2);
            uint32_t bh0 = BHu[bn * ROW_STRIDE + k0];
            uint32_t bh1 = BHu[bn * ROW_STRIDE + k0 + 4];
            uint32_t bl0 = BLu[bn * ROW_STRIDE + k0];
            uint32_t bl1 = BLu[bn * ROW_STRIDE + k0 + 4];
#pragma unroll
            for (int mt = 0; mt < 2; mt++) {
                mma_tf32(acc[mt][nt], ah[mt][0], ah[mt][1], ah[mt][2], ah[mt][3], bh0, bh1);
                mma_tf32(acc[mt][nt], ah[mt][0], ah[mt][1], ah[mt][2], ah[mt][3], bl0, bl1);
                mma_tf32(acc[mt][nt], al[mt][0], al[mt][1], al[mt][2], al[mt][3], bh0, bh1);
            }
        }
    }
}

// ---- kernel 2: HMMA tile sweep, cp.async double-buffered ----
__global__ __launch_bounds__(256, 1)
void dcor_mma_kernel() {
    const int bi = blockIdx.y, bj = blockIdx.x;
    if (bj < bi) return;

    extern __shared__ float sm[];
    const uint32_t smb = smem_u32(sm);
    float* dT = sm + OFF_DT;
    float* NI = sm + OFF_NI;
    float* NJ = sm + OFF_NJ;
    float* COLP = sm + OFF_COLP;
    float* ROWP = sm + OFF_ROWP;

    const int tid = threadIdx.x, warp = tid >> 5, lane = tid & 31;
    const bool diag = (bi == bj);
    const int I = bi * TILE, J = bj * TILE;
    const int mwarp = warp & 3, nhalf = warp >> 2;
    const unsigned FULL = 0xffffffffu;

    double s_aa = 0.0, s_bb = 0.0, s_ab = 0.0;

    // prefetch stage-0 chunk0 into buf0
    issue_chunk(smb, 0, g_xh, g_xl, I, J, 0, tid);

#pragma unroll
    for (int g = 0; g < 2; g++) {
        const float* srch = g ? g_yh : g_xh;
        const float* srcl = g ? g_yl : g_xl;
        const float* nrm  = g ? g_norm_y : g_norm_x;
        double* grs = g ? g_rs_b : g_rs_a;

        if (tid < 128) { NI[tid] = nrm[I + tid]; NJ[tid] = nrm[J + tid]; }

        float acc[2][8][4];
#pragma unroll
        for (int mt = 0; mt < 2; mt++)
#pragma unroll
            for (int nt = 0; nt < 8; nt++)
#pragma unroll
                for (int q = 0; q < 4; q++) acc[mt][nt][q] = 0.f;

        // 4 chunks of 32 k, alternating buffers; each iteration prefetches the
        // next chunk (wrapping into the next stage's chunk0) before waiting.
#pragma unroll
        for (int c = 0; c < 4; c++) {
            const int buf = c & 1;
            const bool last = (g == 1) && (c == 3);
            if (!last) {
                // next chunk: (g, c+1) or (1, 0) when c==3 of stage 0
                if (c < 3) {
                    issue_chunk(smb, buf ^ 1, srch, srcl, I, J, (c + 1) * 32, tid);
                } else {
                    issue_chunk(smb, buf ^ 1, g_yh, g_yl, I, J, 0, tid);
                }
                CP_WAIT(1);     // current chunk done, next may be in flight
            } else {
                CP_WAIT(0);     // final chunk done
            }
            __syncthreads();    // chunk data visible to all warps
            mma_buffer(sm, buf, acc, mwarp, nhalf, lane);
            if (!last) __syncthreads();   // buffer free before it is refilled
        }

        // ---- epilogue: distances + register-side sums ----
        float ssq = 0.f, sab = 0.f;
        float colp[8][2];
        float rowp[2][2] = {{0.f, 0.f}, {0.f, 0.f}};
#pragma unroll
        for (int nt = 0; nt < 8; nt++) { colp[nt][0] = 0.f; colp[nt][1] = 0.f; }

#pragma unroll
        for (int mt = 0; mt < 2; mt++) {
#pragma unroll
            for (int pr = 0; pr < 2; pr++) {
                const int row = mwarp * 32 + mt * 16 + pr * 8 + (lane >> 2);
                const float nIr = NI[row];
#pragma unroll
                for (int nt = 0; nt < 8; nt++) {
                    const int col = nhalf * 64 + nt * 8 + (lane & 3) * 2;
                    float g0 = acc[mt][nt][pr * 2 + 0];
                    float g1 = acc[mt][nt][pr * 2 + 1];
                    float sq0 = fmaf(-2.f, g0, nIr + NJ[col]);
                    float sq1 = fmaf(-2.f, g1, nIr + NJ[col + 1]);
                    float dv0 = (sq0 > 0.f) ? sq0 * rsqrtf(sq0) : 0.f;
                    float dv1 = (sq1 > 0.f) ? sq1 * rsqrtf(sq1) : 0.f;
                    if (diag) {
                        if (row == col)     dv0 = 0.f;
                        if (row == col + 1) dv1 = 0.f;
                    }
                    float* dst = &dT[row * DT_LD + col];
                    if (g == 0) {
                        float2 o; o.x = dv0; o.y = dv1;
                        *reinterpret_cast<float2*>(dst) = o;
                    } else {
                        float2 dx = *reinterpret_cast<const float2*>(dst);
                        sab = fmaf(dx.x, dv0, sab);
                        sab = fmaf(dx.y, dv1, sab);
                    }
                    ssq = fmaf(dv0, dv0, ssq);
                    ssq = fmaf(dv1, dv1, ssq);
                    rowp[mt][pr] += dv0 + dv1;
                    colp[nt][0] += dv0;
                    colp[nt][1] += dv1;
                }
            }
        }
        if (g == 0) { s_aa += (double)ssq; }
        else        { s_bb += (double)ssq; s_ab += (double)sab; }

        // col sums: reduce over the 8 row-lanes (stride-4 lanes)
#pragma unroll
        for (int nt = 0; nt < 8; nt++)
#pragma unroll
            for (int c2 = 0; c2 < 2; c2++) {
                float v = colp[nt][c2];
                v += __shfl_down_sync(FULL, v, 16);
                v += __shfl_down_sync(FULL, v, 8);
                v += __shfl_down_sync(FULL, v, 4);
                colp[nt][c2] = v;
            }
        if (lane < 4) {
#pragma unroll
            for (int nt = 0; nt < 8; nt++) {
                const int col = nhalf * 64 + nt * 8 + lane * 2;
                COLP[mwarp * 128 + col]     = colp[nt][0];
                COLP[mwarp * 128 + col + 1] = colp[nt][1];
            }
        }
        // row sums: reduce over the 4 col-lanes
#pragma unroll
        for (int mt = 0; mt < 2; mt++)
#pragma unroll
            for (int pr = 0; pr < 2; pr++) {
                float v = rowp[mt][pr];
                v += __shfl_down_sync(FULL, v, 1);
                v += __shfl_down_sync(FULL, v, 2);
                rowp[mt][pr] = v;
            }
        if ((lane & 3) == 0) {
#pragma unroll
            for (int mt = 0; mt < 2; mt++)
#pragma unroll
                for (int pr = 0; pr < 2; pr++) {
                    const int row = mwarp * 32 + mt * 16 + pr * 8 + (lane >> 2);
                    ROWP[nhalf * 128 + row] = rowp[mt][pr];
                }
        }
        __syncthreads();
        if (tid < 128) {
            float cs = COLP[tid] + COLP[128 + tid] + COLP[256 + tid] + COLP[384 + tid];
            float rs = ROWP[tid] + ROWP[128 + tid];
            atomicAdd(&grs[I + tid], (double)rs);
            if (!diag) atomicAdd(&grs[J + tid], (double)cs);
        }
        __syncthreads();   // COLP/ROWP + buffers free for next stage
    }

    // ---- block scalar reduction ----
    const double w = diag ? 1.0 : 2.0;
    s_aa *= w; s_bb *= w; s_ab *= w;
#pragma unroll
    for (int o = 16; o; o >>= 1) {
        s_aa += __shfl_down_sync(FULL, s_aa, o);
        s_bb += __shfl_down_sync(FULL, s_bb, o);
        s_ab += __shfl_down_sync(FULL, s_ab, o);
    }
    __shared__ double redS[3][8];
    if (lane == 0) { redS[0][warp] = s_aa; redS[1][warp] = s_bb; redS[2][warp] = s_ab; }
    __syncthreads();
    if (tid == 0) {
        double a = 0, b = 0, c = 0;
#pragma unroll
        for (int k = 0; k < 8; k++) { a += redS[0][k]; b += redS[1][k]; c += redS[2][k]; }
        atomicAdd(&g_S[0], a);
        atomicAdd(&g_S[1], b);
        atomicAdd(&g_S[2], c);
    }
}

// ---- kernel 3: combine + final scalar ----
__global__ void finalize_kernel(float* __restrict__ out) {
    int tid = threadIdx.x;
    double dAB = 0, dAA = 0, dBB = 0, Ta = 0, Tb = 0;
    for (int i = tid; i < NPTS; i += 256) {
        double a = g_rs_a[i], b = g_rs_b[i];
        dAB += a * b; dAA += a * a; dBB += b * b; Ta += a; Tb += b;
    }
    const unsigned FULL = 0xffffffffu;
#pragma unroll
    for (int o = 16; o; o >>= 1) {
        dAB += __shfl_down_sync(FULL, dAB, o);
        dAA += __shfl_down_sync(FULL, dAA, o);
        dBB += __shfl_down_sync(FULL, dBB, o);
        Ta  += __shfl_down_sync(FULL, Ta,  o);
        Tb  += __shfl_down_sync(FULL, Tb,  o);
    }
    __shared__ double red[5][8];
    int wid = tid >> 5, lane = tid & 31;
    if (lane == 0) {
        red[0][wid] = dAB; red[1][wid] = dAA; red[2][wid] = dBB;
        red[3][wid] = Ta;  red[4][wid] = Tb;
    }
    __syncthreads();
    if (tid == 0) {
        double sAB = 0, sAA = 0, sBB = 0, ta = 0, tb = 0;
#pragma unroll
        for (int k = 0; k < 8; k++) {
            sAB += red[0][k]; sAA += red[1][k]; sBB += red[2][k];
            ta  += red[3][k]; tb  += red[4][k];
        }
        const double n = (double)NPTS;
        const double inv_n2 = 1.0 / (n * n);
        double xy = (g_S[2] - (2.0 / n) * sAB + ta * tb * inv_n2) * inv_n2;
        double xx = (g_S[0] - (2.0 / n) * sAA + ta * ta * inv_n2) * inv_n2;
        double yy = (g_S[1] - (2.0 / n) * sBB + tb * tb * inv_n2) * inv_n2;
        xy = fmax(xy, 0.0); xx = fmax(xx, 0.0); yy = fmax(yy, 0.0);
        double dcor = -sqrt(xy) / sqrt(sqrt(xx) * sqrt(yy));
        out[0] = (float)dcor;
    }
}

extern "C" void kernel_launch(void* const* d_in, const int* in_sizes, int n_in,
                              void* d_out, int out_size) {
    (void)in_sizes; (void)n_in; (void)out_size;
    const float* x = (const float*)d_in[0];
    const float* y = (const float*)d_in[1];
    float* out = (float*)d_out;

    cudaFuncSetAttribute(dcor_mma_kernel,
                         cudaFuncAttributeMaxDynamicSharedMemorySize, SMEM_BYTES);

    prep_kernel<<<NPTS / 8, 256>>>(x, y);
    dim3 grid(NB, NB);
    dcor_mma_kernel<<<grid, 256, SMEM_BYTES>>>();
    finalize_kernel<<<1, 256>>>(out);
}

// round 7
// speedup vs baseline: 2.1288x; 1.1638x over previous
#include <cuda_runtime.h>
#include <math.h>
#include <stdint.h>

#define NPTS 8192
#define DIMS 128
#define TILE 128
#define NB   (NPTS / TILE)   // 64

// ---- smem layout (floats) ----
// double-buffered 32-k chunk operands: [2 bufs][4 arrays][128 rows][36]
#define ROW_STRIDE 36
#define ARR_STRIDE (128 * ROW_STRIDE)  // 4608
#define BUF_STRIDE (4 * ARR_STRIDE)    // 18432
#define OFF_NIX   (2 * BUF_STRIDE)     // 36864
#define OFF_NJX   (OFF_NIX + 128)
#define OFF_NIY   (OFF_NJX + 128)
#define OFF_NJY   (OFF_NIY + 128)
#define OFF_COLPA (OFF_NJY + 128)      // [4][128]
#define OFF_COLPB (OFF_COLPA + 512)    // [4][128]
#define OFF_ROWPA (OFF_COLPB + 512)    // [2][128]
#define OFF_ROWPB (OFF_ROWPA + 256)    // [2][128]
#define SMEM_FLOATS (OFF_ROWPB + 256)  // 38912
#define SMEM_BYTES  (SMEM_FLOATS * 4)  // 155648

// ---- global scratch (16B aligned for cp.async) ----
__device__ __align__(16) float g_xh[NPTS * DIMS];
__device__ __align__(16) float g_xl[NPTS * DIMS];
__device__ __align__(16) float g_yh[NPTS * DIMS];
__device__ __align__(16) float g_yl[NPTS * DIMS];
__device__ float  g_norm_x[NPTS];
__device__ float  g_norm_y[NPTS];
__device__ double g_rs_a[NPTS];
__device__ double g_rs_b[NPTS];
__device__ double g_S[3];   // [0]=Sum dx^2, [1]=Sum dy^2, [2]=Sum dx*dy

// ---- helpers ----
__device__ __forceinline__ void mma_tf32(float* d,
                                         uint32_t a0, uint32_t a1, uint32_t a2, uint32_t a3,
                                         uint32_t b0, uint32_t b1) {
    asm volatile(
        "mma.sync.aligned.m16n8k8.row.col.f32.tf32.tf32.f32 "
        "{%0,%1,%2,%3}, {%4,%5,%6,%7}, {%8,%9}, {%0,%1,%2,%3};"
        : "+f"(d[0]), "+f"(d[1]), "+f"(d[2]), "+f"(d[3])
        : "r"(a0), "r"(a1), "r"(a2), "r"(a3), "r"(b0), "r"(b1));
}

__device__ __forceinline__ uint32_t smem_u32(const void* p) {
    uint32_t a;
    asm("{ .reg .u64 t; cvta.to.shared.u64 t, %1; cvt.u32.u64 %0, t; }" : "=r"(a) : "l"(p));
    return a;
}
__device__ __forceinline__ void cpa16(uint32_t dst, const float* src) {
    asm volatile("cp.async.ca.shared.global [%0], [%1], 16;" :: "r"(dst), "l"(src));
}
#define CP_COMMIT() asm volatile("cp.async.commit_group;" ::: "memory")
#define CP_WAIT(N)  asm volatile("cp.async.wait_group %0;" :: "n"(N) : "memory")

__device__ __forceinline__ void split_tf32(float v, float& hi, float& lo) {
    hi = __uint_as_float(__float_as_uint(v) & 0xffffe000u);
    float l = v - hi;
    lo = __uint_as_float(__float_as_uint(l) & 0xffffe000u);
}

// ---- kernel 1: pre-split x/y into tf32 hi/lo + norms + zero scratch ----
__global__ __launch_bounds__(256, 4)
void prep_kernel(const float* __restrict__ x, const float* __restrict__ y) {
    const int warp = threadIdx.x >> 5, lane = threadIdx.x & 31;
    const int r = blockIdx.x * 8 + warp;
    if (blockIdx.x == 0 && threadIdx.x < 3) g_S[threadIdx.x] = 0.0;

    const float4 vx = reinterpret_cast<const float4*>(x + (size_t)r * DIMS)[lane];
    const float4 vy = reinterpret_cast<const float4*>(y + (size_t)r * DIMS)[lane];
    float4 h, l;
    split_tf32(vx.x, h.x, l.x); split_tf32(vx.y, h.y, l.y);
    split_tf32(vx.z, h.z, l.z); split_tf32(vx.w, h.w, l.w);
    reinterpret_cast<float4*>(g_xh + (size_t)r * DIMS)[lane] = h;
    reinterpret_cast<float4*>(g_xl + (size_t)r * DIMS)[lane] = l;
    float sx = vx.x * vx.x + vx.y * vx.y + vx.z * vx.z + vx.w * vx.w;

    split_tf32(vy.x, h.x, l.x); split_tf32(vy.y, h.y, l.y);
    split_tf32(vy.z, h.z, l.z); split_tf32(vy.w, h.w, l.w);
    reinterpret_cast<float4*>(g_yh + (size_t)r * DIMS)[lane] = h;
    reinterpret_cast<float4*>(g_yl + (size_t)r * DIMS)[lane] = l;
    float sy = vy.x * vy.x + vy.y * vy.y + vy.z * vy.z + vy.w * vy.w;

    const unsigned FULL = 0xffffffffu;
#pragma unroll
    for (int o = 16; o; o >>= 1) {
        sx += __shfl_xor_sync(FULL, sx, o);
        sy += __shfl_xor_sync(FULL, sy, o);
    }
    if (lane == 0) {
        g_norm_x[r] = sx; g_norm_y[r] = sy;
        g_rs_a[r] = 0.0;  g_rs_b[r] = 0.0;
    }
}

// issue cp.async for chunk n: matrix = n&1 (0=x, 1=y), kc = (n>>1)*32, buf = n&1
__device__ __forceinline__ void issue_chunk_n(uint32_t smb, int n, int I, int J, int tid) {
    const float* srch = (n & 1) ? g_yh : g_xh;
    const float* srcl = (n & 1) ? g_yl : g_xl;
    const int kc = (n >> 1) * 32;
    const uint32_t base = smb + (uint32_t)((n & 1) * BUF_STRIDE) * 4u;
#pragma unroll
    for (int i = 0; i < 4; i++) {           // 128 rows * 8 float4 / 256 threads
        const int t  = tid + i * 256;
        const int r  = t >> 3;              // row 0..127
        const int k4 = t & 7;               // float4 0..7
        const uint32_t d = base + (uint32_t)(r * ROW_STRIDE + k4 * 4) * 4u;
        const int so = r * DIMS + kc + k4 * 4;
        cpa16(d,                        srch + (size_t)I * DIMS + so);
        cpa16(d + ARR_STRIDE * 4u,      srcl + (size_t)I * DIMS + so);
        cpa16(d + 2u * ARR_STRIDE * 4u, srch + (size_t)J * DIMS + so);
        cpa16(d + 3u * ARR_STRIDE * 4u, srcl + (size_t)J * DIMS + so);
    }
    CP_COMMIT();
}

// run 4 k-steps (32 k) of MMA over one buffer into the given accumulator set
__device__ __forceinline__ void mma_buffer(const float* __restrict__ sm, int buf,
                                           float (*acc)[8][4], int mwarp, int nhalf, int lane) {
    const uint32_t* AHu = reinterpret_cast<const uint32_t*>(sm + buf * BUF_STRIDE);
    const uint32_t* ALu = AHu + ARR_STRIDE;
    const uint32_t* BHu = AHu + 2 * ARR_STRIDE;
    const uint32_t* BLu = AHu + 3 * ARR_STRIDE;
#pragma unroll
    for (int ks = 0; ks < 4; ks++) {
        const int k0 = ks * 8 + (lane & 3);
        uint32_t ah[2][4], al[2][4];
#pragma unroll
        for (int mt = 0; mt < 2; mt++) {
            const int ar = mwarp * 32 + mt * 16 + (lane >> 2);
            ah[mt][0] = AHu[ar * ROW_STRIDE + k0];
            ah[mt][1] = AHu[(ar + 8) * ROW_STRIDE + k0];
            ah[mt][2] = AHu[ar * ROW_STRIDE + k0 + 4];
            ah[mt][3] = AHu[(ar + 8) * ROW_STRIDE + k0 + 4];
            al[mt][0] = ALu[ar * ROW_STRIDE + k0];
            al[mt][1] = ALu[(ar + 8) * ROW_STRIDE + k0];
            al[mt][2] = ALu[ar * ROW_STRIDE + k0 + 4];
            al[mt][3] = ALu[(ar + 8) * ROW_STRIDE + k0 + 4];
        }
#pragma unroll
        for (int nt = 0; nt < 8; nt++) {
            const int bn = nhalf * 64 + nt * 8 + (lane >> 2);
            uint32_t bh0 = BHu[bn * ROW_STRIDE + k0];
            uint32_t bh1 = BHu[bn * ROW_STRIDE + k0 + 4];
            uint32_t bl0 = BLu[bn * ROW_STRIDE + k0];
            uint32_t bl1 = BLu[bn * ROW_STRIDE + k0 + 4];
#pragma unroll
            for (int mt = 0; mt < 2; mt++) {
                mma_tf32(acc[mt][nt], ah[mt][0], ah[mt][1], ah[mt][2], ah[mt][3], bh0, bh1);
                mma_tf32(acc[mt][nt], ah[mt][0], ah[mt][1], ah[mt][2], ah[mt][3], bl0, bl1);
                mma_tf32(acc[mt][nt], al[mt][0], al[mt][1], al[mt][2], al[mt][3], bh0, bh1);
            }
        }
    }
}

// ---- kernel 2: fused X/Y HMMA tile sweep (cross product in registers) ----
__global__ __launch_bounds__(256, 1)
void dcor_mma_kernel() {
    const int bi = blockIdx.y, bj = blockIdx.x;
    if (bj < bi) return;

    extern __shared__ float sm[];
    const uint32_t smb = smem_u32(sm);
    float* NIX = sm + OFF_NIX;
    float* NJX = sm + OFF_NJX;
    float* NIY = sm + OFF_NIY;
    float* NJY = sm + OFF_NJY;
    float* COLPA = sm + OFF_COLPA;
    float* COLPB = sm + OFF_COLPB;
    float* ROWPA = sm + OFF_ROWPA;
    float* ROWPB = sm + OFF_ROWPB;

    const int tid = threadIdx.x, warp = tid >> 5, lane = tid & 31;
    const bool diag = (bi == bj);
    const int I = bi * TILE, J = bj * TILE;
    const int mwarp = warp & 3, nhalf = warp >> 2;
    const unsigned FULL = 0xffffffffu;

    // prefetch chunk0 (x, kc=0 -> buf0) and chunk1 (y, kc=0 -> buf1)
    issue_chunk_n(smb, 0, I, J, tid);
    issue_chunk_n(smb, 1, I, J, tid);

    if (tid < 128) {
        NIX[tid] = g_norm_x[I + tid]; NJX[tid] = g_norm_x[J + tid];
        NIY[tid] = g_norm_y[I + tid]; NJY[tid] = g_norm_y[J + tid];
    }

    float acc_x[2][8][4], acc_y[2][8][4];
#pragma unroll
    for (int mt = 0; mt < 2; mt++)
#pragma unroll
        for (int nt = 0; nt < 8; nt++)
#pragma unroll
            for (int q = 0; q < 4; q++) { acc_x[mt][nt][q] = 0.f; acc_y[mt][nt][q] = 0.f; }

    // 8 chunks: x0,y0,x1,y1,x2,y2,x3,y3 alternating buffers.
#pragma unroll
    for (int c = 0; c < 8; c++) {
        const int buf = c & 1;
        if (c < 7) { CP_WAIT(1); } else { CP_WAIT(0); }
        __syncthreads();   // chunk c visible
        mma_buffer(sm, buf, (c & 1) ? acc_y : acc_x, mwarp, nhalf, lane);
        if (c < 6) {
            __syncthreads();              // all warps done reading buf
            issue_chunk_n(smb, c + 2, I, J, tid);
        }
    }

    // ---- fused epilogue: dx & dy from registers, cross product local ----
    float ssa = 0.f, ssb = 0.f, sab = 0.f;
    float colpa[8][2], colpb[8][2];
    float rowpa[2][2] = {{0.f, 0.f}, {0.f, 0.f}};
    float rowpb[2][2] = {{0.f, 0.f}, {0.f, 0.f}};
#pragma unroll
    for (int nt = 0; nt < 8; nt++) {
        colpa[nt][0] = 0.f; colpa[nt][1] = 0.f;
        colpb[nt][0] = 0.f; colpb[nt][1] = 0.f;
    }

#pragma unroll
    for (int mt = 0; mt < 2; mt++) {
#pragma unroll
        for (int pr = 0; pr < 2; pr++) {
            const int row = mwarp * 32 + mt * 16 + pr * 8 + (lane >> 2);
            const float nIx = NIX[row];
            const float nIy = NIY[row];
#pragma unroll
            for (int nt = 0; nt < 8; nt++) {
                const int col = nhalf * 64 + nt * 8 + (lane & 3) * 2;
                float gx0 = acc_x[mt][nt][pr * 2 + 0];
                float gx1 = acc_x[mt][nt][pr * 2 + 1];
                float gy0 = acc_y[mt][nt][pr * 2 + 0];
                float gy1 = acc_y[mt][nt][pr * 2 + 1];
                float sqx0 = fmaf(-2.f, gx0, nIx + NJX[col]);
                float sqx1 = fmaf(-2.f, gx1, nIx + NJX[col + 1]);
                float sqy0 = fmaf(-2.f, gy0, nIy + NJY[col]);
                float sqy1 = fmaf(-2.f, gy1, nIy + NJY[col + 1]);
                float dx0 = (sqx0 > 0.f) ? sqx0 * rsqrtf(sqx0) : 0.f;
                float dx1 = (sqx1 > 0.f) ? sqx1 * rsqrtf(sqx1) : 0.f;
                float dy0 = (sqy0 > 0.f) ? sqy0 * rsqrtf(sqy0) : 0.f;
                float dy1 = (sqy1 > 0.f) ? sqy1 * rsqrtf(sqy1) : 0.f;
                if (diag) {
                    if (row == col)     { dx0 = 0.f; dy0 = 0.f; }
                    if (row == col + 1) { dx1 = 0.f; dy1 = 0.f; }
                }
                ssa = fmaf(dx0, dx0, ssa); ssa = fmaf(dx1, dx1, ssa);
                ssb = fmaf(dy0, dy0, ssb); ssb = fmaf(dy1, dy1, ssb);
                sab = fmaf(dx0, dy0, sab); sab = fmaf(dx1, dy1, sab);
                rowpa[mt][pr] += dx0 + dx1;
                rowpb[mt][pr] += dy0 + dy1;
                colpa[nt][0] += dx0; colpa[nt][1] += dx1;
                colpb[nt][0] += dy0; colpb[nt][1] += dy1;
            }
        }
    }
    double s_aa = (double)ssa, s_bb = (double)ssb, s_ab = (double)sab;

    // col sums: reduce over the 8 row-lanes (stride-4 lanes)
#pragma unroll
    for (int nt = 0; nt < 8; nt++)
#pragma unroll
        for (int c2 = 0; c2 < 2; c2++) {
            float va = colpa[nt][c2], vb = colpb[nt][c2];
            va += __shfl_down_sync(FULL, va, 16);
            va += __shfl_down_sync(FULL, va, 8);
            va += __shfl_down_sync(FULL, va, 4);
            vb += __shfl_down_sync(FULL, vb, 16);
            vb += __shfl_down_sync(FULL, vb, 8);
            vb += __shfl_down_sync(FULL, vb, 4);
            colpa[nt][c2] = va; colpb[nt][c2] = vb;
        }
    if (lane < 4) {
#pragma unroll
        for (int nt = 0; nt < 8; nt++) {
            const int col = nhalf * 64 + nt * 8 + lane * 2;
            COLPA[mwarp * 128 + col]     = colpa[nt][0];
            COLPA[mwarp * 128 + col + 1] = colpa[nt][1];
            COLPB[mwarp * 128 + col]     = colpb[nt][0];
            COLPB[mwarp * 128 + col + 1] = colpb[nt][1];
        }
    }
    // row sums: reduce over the 4 col-lanes
#pragma unroll
    for (int mt = 0; mt < 2; mt++)
#pragma unroll
        for (int pr = 0; pr < 2; pr++) {
            float va = rowpa[mt][pr], vb = rowpb[mt][pr];
            va += __shfl_down_sync(FULL, va, 1);
            va += __shfl_down_sync(FULL, va, 2);
            vb += __shfl_down_sync(FULL, vb, 1);
            vb += __shfl_down_sync(FULL, vb, 2);
            rowpa[mt][pr] = va; rowpb[mt][pr] = vb;
        }
    if ((lane & 3) == 0) {
#pragma unroll
        for (int mt = 0; mt < 2; mt++)
#pragma unroll
            for (int pr = 0; pr < 2; pr++) {
                const int row = mwarp * 32 + mt * 16 + pr * 8 + (lane >> 2);
                ROWPA[nhalf * 128 + row] = rowpa[mt][pr];
                ROWPB[nhalf * 128 + row] = rowpb[mt][pr];
            }
    }
    __syncthreads();
    if (tid < 128) {
        float csa = COLPA[tid] + COLPA[128 + tid] + COLPA[256 + tid] + COLPA[384 + tid];
        float csb = COLPB[tid] + COLPB[128 + tid] + COLPB[256 + tid] + COLPB[384 + tid];
        float rsa = ROWPA[tid] + ROWPA[128 + tid];
        float rsb = ROWPB[tid] + ROWPB[128 + tid];
        atomicAdd(&g_rs_a[I + tid], (double)rsa);
        atomicAdd(&g_rs_b[I + tid], (double)rsb);
        if (!diag) {
            atomicAdd(&g_rs_a[J + tid], (double)csa);
            atomicAdd(&g_rs_b[J + tid], (double)csb);
        }
    }

    // ---- block scalar reduction ----
    const double w = diag ? 1.0 : 2.0;
    s_aa *= w; s_bb *= w; s_ab *= w;
#pragma unroll
    for (int o = 16; o; o >>= 1) {
        s_aa += __shfl_down_sync(FULL, s_aa, o);
        s_bb += __shfl_down_sync(FULL, s_bb, o);
        s_ab += __shfl_down_sync(FULL, s_ab, o);
    }
    __shared__ double redS[3][8];
    if (lane == 0) { redS[0][warp] = s_aa; redS[1][warp] = s_bb; redS[2][warp] = s_ab; }
    __syncthreads();
    if (tid == 0) {
        double a = 0, b = 0, c = 0;
#pragma unroll
        for (int k = 0; k < 8; k++) { a += redS[0][k]; b += redS[1][k]; c += redS[2][k]; }
        atomicAdd(&g_S[0], a);
        atomicAdd(&g_S[1], b);
        atomicAdd(&g_S[2], c);
    }
}

// ---- kernel 3: combine + final scalar ----
__global__ void finalize_kernel(float* __restrict__ out) {
    int tid = threadIdx.x;
    double dAB = 0, dAA = 0, dBB = 0, Ta = 0, Tb = 0;
    for (int i = tid; i < NPTS; i += 256) {
        double a = g_rs_a[i], b = g_rs_b[i];
        dAB += a * b; dAA += a * a; dBB += b * b; Ta += a; Tb += b;
    }
    const unsigned FULL = 0xffffffffu;
#pragma unroll
    for (int o = 16; o; o >>= 1) {
        dAB += __shfl_down_sync(FULL, dAB, o);
        dAA += __shfl_down_sync(FULL, dAA, o);
        dBB += __shfl_down_sync(FULL, dBB, o);
        Ta  += __shfl_down_sync(FULL, Ta,  o);
        Tb  += __shfl_down_sync(FULL, Tb,  o);
    }
    __shared__ double red[5][8];
    int wid = tid >> 5, lane = tid & 31;
    if (lane == 0) {
        red[0][wid] = dAB; red[1][wid] = dAA; red[2][wid] = dBB;
        red[3][wid] = Ta;  red[4][wid] = Tb;
    }
    __syncthreads();
    if (tid == 0) {
        double sAB = 0, sAA = 0, sBB = 0, ta = 0, tb = 0;
#pragma unroll
        for (int k = 0; k < 8; k++) {
            sAB += red[0][k]; sAA += red[1][k]; sBB += red[2][k];
            ta  += red[3][k]; tb  += red[4][k];
        }
        const double n = (double)NPTS;
        const double inv_n2 = 1.0 / (n * n);
        double xy = (g_S[2] - (2.0 / n) * sAB + ta * tb * inv_n2) * inv_n2;
        double xx = (g_S[0] - (2.0 / n) * sAA + ta * ta * inv_n2) * inv_n2;
        double yy = (g_S[1] - (2.0 / n) * sBB + tb * tb * inv_n2) * inv_n2;
        xy = fmax(xy, 0.0); xx = fmax(xx, 0.0); yy = fmax(yy, 0.0);
        double dcor = -sqrt(xy) / sqrt(sqrt(xx) * sqrt(yy));
        out[0] = (float)dcor;
    }
}

extern "C" void kernel_launch(void* const* d_in, const int* in_sizes, int n_in,
                              void* d_out, int out_size) {
    (void)in_sizes; (void)n_in; (void)out_size;
    const float* x = (const float*)d_in[0];
    const float* y = (const float*)d_in[1];
    float* out = (float*)d_out;

    cudaFuncSetAttribute(dcor_mma_kernel,
                         cudaFuncAttributeMaxDynamicSharedMemorySize, SMEM_BYTES);

    prep_kernel<<<NPTS / 8, 256>>>(x, y);
    dim3 grid(NB, NB);
    dcor_mma_kernel<<<grid, 256, SMEM_BYTES>>>();
    finalize_kernel<<<1, 256>>>(out);
}

// round 8
// speedup vs baseline: 3.5515x; 1.6683x over previous
#include <cuda_runtime.h>
#include <cuda_bf16.h>
#include <math.h>
#include <stdint.h>

#define NPTS 8192
#define DIMS 128
#define TILE 128
#define NB   (NPTS / TILE)   // 64

// ---- smem layout (bytes) ----
// double-buffered 64-k bf16 chunk operands: [2 bufs][4 arrays][128 rows][144B]
#define ROW_BYTES 144                  // 64 bf16 = 128B + 16B pad (conflict-free LDSM)
#define ARR_BYTES (128 * ROW_BYTES)    // 18432
#define ARR_AH 0
#define ARR_AM (1 * ARR_BYTES)
#define ARR_BH (2 * ARR_BYTES)
#define ARR_BM (3 * ARR_BYTES)
#define BUF_BYTES (4 * ARR_BYTES)      // 73728
// float-indexed tail arrays after the two buffers (147456 B = 36864 floats)
#define OFF_NIX   36864
#define OFF_NJX   (OFF_NIX + 128)
#define OFF_NIY   (OFF_NJX + 128)
#define OFF_NJY   (OFF_NIY + 128)
#define OFF_COLPA (OFF_NJY + 128)      // [4][128]
#define OFF_COLPB (OFF_COLPA + 512)    // [4][128]
#define OFF_ROWPA (OFF_COLPB + 512)    // [2][128]
#define OFF_ROWPB (OFF_ROWPA + 256)    // [2][128]
#define SMEM_FLOATS (OFF_ROWPB + 256)  // 38912
#define SMEM_BYTES  (SMEM_FLOATS * 4)  // 155648

// ---- global scratch (bf16 hi/mid split; 16B aligned for cp.async) ----
__device__ __align__(16) __nv_bfloat16 g_xh[NPTS * DIMS];
__device__ __align__(16) __nv_bfloat16 g_xm[NPTS * DIMS];
__device__ __align__(16) __nv_bfloat16 g_yh[NPTS * DIMS];
__device__ __align__(16) __nv_bfloat16 g_ym[NPTS * DIMS];
__device__ float  g_norm_x[NPTS];
__device__ float  g_norm_y[NPTS];
__device__ double g_rs_a[NPTS];
__device__ double g_rs_b[NPTS];
__device__ double g_S[3];   // [0]=Sum dx^2, [1]=Sum dy^2, [2]=Sum dx*dy

// ---- helpers ----
__device__ __forceinline__ void mma_bf16(float* d,
                                         uint32_t a0, uint32_t a1, uint32_t a2, uint32_t a3,
                                         uint32_t b0, uint32_t b1) {
    asm volatile(
        "mma.sync.aligned.m16n8k16.row.col.f32.bf16.bf16.f32 "
        "{%0,%1,%2,%3}, {%4,%5,%6,%7}, {%8,%9}, {%0,%1,%2,%3};"
        : "+f"(d[0]), "+f"(d[1]), "+f"(d[2]), "+f"(d[3])
        : "r"(a0), "r"(a1), "r"(a2), "r"(a3), "r"(b0), "r"(b1));
}

__device__ __forceinline__ void ldsm4(uint32_t* r, uint32_t addr) {
    asm volatile("ldmatrix.sync.aligned.m8n8.x4.shared.b16 {%0,%1,%2,%3}, [%4];"
        : "=r"(r[0]), "=r"(r[1]), "=r"(r[2]), "=r"(r[3]) : "r"(addr));
}

__device__ __forceinline__ uint32_t smem_u32(const void* p) {
    uint32_t a;
    asm("{ .reg .u64 t; cvta.to.shared.u64 t, %1; cvt.u32.u64 %0, t; }" : "=r"(a) : "l"(p));
    return a;
}
__device__ __forceinline__ void cpa16(uint32_t dst, const void* src) {
    asm volatile("cp.async.ca.shared.global [%0], [%1], 16;" :: "r"(dst), "l"(src));
}
#define CP_COMMIT() asm volatile("cp.async.commit_group;" ::: "memory")
#define CP_WAIT(N)  asm volatile("cp.async.wait_group %0;" :: "n"(N) : "memory")

// split fp32 -> bf16 hi + bf16 mid (Ootomo-style 2-term split)
__device__ __forceinline__ void split_bf16(float v, __nv_bfloat16& h, __nv_bfloat16& m) {
    h = __float2bfloat16_rn(v);
    m = __float2bfloat16_rn(v - __bfloat162float(h));
}

// ---- kernel 1: pre-split x/y into bf16 h/m + norms + zero scratch ----
__global__ __launch_bounds__(256, 4)
void prep_kernel(const float* __restrict__ x, const float* __restrict__ y) {
    const int warp = threadIdx.x >> 5, lane = threadIdx.x & 31;
    const int r = blockIdx.x * 8 + warp;
    if (blockIdx.x == 0 && threadIdx.x < 3) g_S[threadIdx.x] = 0.0;

    const float4 vx = reinterpret_cast<const float4*>(x + (size_t)r * DIMS)[lane];
    const float4 vy = reinterpret_cast<const float4*>(y + (size_t)r * DIMS)[lane];

    __nv_bfloat16 h[4], m[4];
    split_bf16(vx.x, h[0], m[0]); split_bf16(vx.y, h[1], m[1]);
    split_bf16(vx.z, h[2], m[2]); split_bf16(vx.w, h[3], m[3]);
    *reinterpret_cast<uint2*>(g_xh + (size_t)r * DIMS + lane * 4) = *reinterpret_cast<uint2*>(h);
    *reinterpret_cast<uint2*>(g_xm + (size_t)r * DIMS + lane * 4) = *reinterpret_cast<uint2*>(m);
    float sx = vx.x * vx.x + vx.y * vx.y + vx.z * vx.z + vx.w * vx.w;

    split_bf16(vy.x, h[0], m[0]); split_bf16(vy.y, h[1], m[1]);
    split_bf16(vy.z, h[2], m[2]); split_bf16(vy.w, h[3], m[3]);
    *reinterpret_cast<uint2*>(g_yh + (size_t)r * DIMS + lane * 4) = *reinterpret_cast<uint2*>(h);
    *reinterpret_cast<uint2*>(g_ym + (size_t)r * DIMS + lane * 4) = *reinterpret_cast<uint2*>(m);
    float sy = vy.x * vy.x + vy.y * vy.y + vy.z * vy.z + vy.w * vy.w;

    const unsigned FULL = 0xffffffffu;
#pragma unroll
    for (int o = 16; o; o >>= 1) {
        sx += __shfl_xor_sync(FULL, sx, o);
        sy += __shfl_xor_sync(FULL, sy, o);
    }
    if (lane == 0) {
        g_norm_x[r] = sx; g_norm_y[r] = sy;
        g_rs_a[r] = 0.0;  g_rs_b[r] = 0.0;
    }
}

// issue cp.async for chunk n: matrix = n&1 (0=x, 1=y), kc = (n>>1)*64, buf = n&1
__device__ __forceinline__ void issue_chunk_n(uint32_t smb, int n, int I, int J, int tid) {
    const __nv_bfloat16* sh = (n & 1) ? g_yh : g_xh;
    const __nv_bfloat16* sm2 = (n & 1) ? g_ym : g_xm;
    const int kc = (n >> 1) * 64;
    const uint32_t base = smb + (uint32_t)((n & 1) * BUF_BYTES);
#pragma unroll
    for (int i = 0; i < 4; i++) {           // 128 rows * 8 segs / 256 threads
        const int t   = tid + i * 256;
        const int r   = t >> 3;             // row 0..127
        const int seg = t & 7;              // 16B segment (8 bf16)
        const uint32_t d = base + (uint32_t)(r * ROW_BYTES + seg * 16);
        const size_t soI = (size_t)(I + r) * DIMS + kc + seg * 8;
        const size_t soJ = (size_t)(J + r) * DIMS + kc + seg * 8;
        cpa16(d + ARR_AH, sh + soI);
        cpa16(d + ARR_AM, sm2 + soI);
        cpa16(d + ARR_BH, sh + soJ);
        cpa16(d + ARR_BM, sm2 + soJ);
    }
    CP_COMMIT();
}

// run 4 k16-steps of bf16x3 MMA over one buffer into the given accumulator set
__device__ __forceinline__ void mma_chunk(uint32_t smb, int buf,
                                          float (*acc)[8][4], int mwarp, int nhalf, int lane) {
    const uint32_t base = smb + (uint32_t)(buf * BUF_BYTES);
    // ldmatrix lane-address patterns
    // A (m16n16 block): lanes 0-15 -> rows 0-15 @k_lo, 16-31 -> rows 0-15 @k_hi
    const uint32_t aoff = (uint32_t)((mwarp * 32 + (lane & 15)) * ROW_BYTES + (lane >> 4) * 16);
    // B (two n8 blocks x k16): lanes 0-7: n0-7@k_lo, 8-15: n0-7@k_hi, 16-23: n8-15@k_lo, 24-31: n8-15@k_hi
    const uint32_t boff = (uint32_t)((nhalf * 64 + (lane & 7) + ((lane >> 4) & 1) * 8) * ROW_BYTES
                                     + ((lane >> 3) & 1) * 16);
#pragma unroll
    for (int ks = 0; ks < 4; ks++) {
        uint32_t ah[2][4], am[2][4];
#pragma unroll
        for (int mt = 0; mt < 2; mt++) {
            const uint32_t ao = aoff + (uint32_t)(mt * 16 * ROW_BYTES + ks * 32);
            ldsm4(ah[mt], base + ARR_AH + ao);
            ldsm4(am[mt], base + ARR_AM + ao);
        }
#pragma unroll
        for (int ntp = 0; ntp < 4; ntp++) {
            const uint32_t bo = boff + (uint32_t)(ntp * 16 * ROW_BYTES + ks * 32);
            uint32_t bh[4], bm[4];
            ldsm4(bh, base + ARR_BH + bo);
            ldsm4(bm, base + ARR_BM + bo);
#pragma unroll
            for (int mt = 0; mt < 2; mt++) {
                float* a0 = acc[mt][2 * ntp];
                float* a1 = acc[mt][2 * ntp + 1];
                mma_bf16(a0, ah[mt][0], ah[mt][1], ah[mt][2], ah[mt][3], bh[0], bh[1]);
                mma_bf16(a0, ah[mt][0], ah[mt][1], ah[mt][2], ah[mt][3], bm[0], bm[1]);
                mma_bf16(a0, am[mt][0], am[mt][1], am[mt][2], am[mt][3], bh[0], bh[1]);
                mma_bf16(a1, ah[mt][0], ah[mt][1], ah[mt][2], ah[mt][3], bh[2], bh[3]);
                mma_bf16(a1, ah[mt][0], ah[mt][1], ah[mt][2], ah[mt][3], bm[2], bm[3]);
                mma_bf16(a1, am[mt][0], am[mt][1], am[mt][2], am[mt][3], bh[2], bh[3]);
            }
        }
    }
}

// ---- kernel 2: fused X/Y bf16x3 HMMA tile sweep ----
__global__ __launch_bounds__(256, 1)
void dcor_mma_kernel() {
    const int bi = blockIdx.y, bj = blockIdx.x;
    if (bj < bi) return;

    extern __shared__ float sm[];
    const uint32_t smb = smem_u32(sm);
    float* NIX = sm + OFF_NIX;
    float* NJX = sm + OFF_NJX;
    float* NIY = sm + OFF_NIY;
    float* NJY = sm + OFF_NJY;
    float* COLPA = sm + OFF_COLPA;
    float* COLPB = sm + OFF_COLPB;
    float* ROWPA = sm + OFF_ROWPA;
    float* ROWPB = sm + OFF_ROWPB;

    const int tid = threadIdx.x, warp = tid >> 5, lane = tid & 31;
    const bool diag = (bi == bj);
    const int I = bi * TILE, J = bj * TILE;
    const int mwarp = warp & 3, nhalf = warp >> 2;
    const unsigned FULL = 0xffffffffu;

    // prefetch chunk0 (x, k0-63 -> buf0) and chunk1 (y, k0-63 -> buf1)
    issue_chunk_n(smb, 0, I, J, tid);
    issue_chunk_n(smb, 1, I, J, tid);

    if (tid < 128) {
        NIX[tid] = g_norm_x[I + tid]; NJX[tid] = g_norm_x[J + tid];
        NIY[tid] = g_norm_y[I + tid]; NJY[tid] = g_norm_y[J + tid];
    }

    float acc_x[2][8][4], acc_y[2][8][4];
#pragma unroll
    for (int mt = 0; mt < 2; mt++)
#pragma unroll
        for (int nt = 0; nt < 8; nt++)
#pragma unroll
            for (int q = 0; q < 4; q++) { acc_x[mt][nt][q] = 0.f; acc_y[mt][nt][q] = 0.f; }

    // 4 chunks: x[k0:64], y[k0:64], x[k64:128], y[k64:128]
#pragma unroll
    for (int c = 0; c < 4; c++) {
        if (c < 3) { CP_WAIT(1); } else { CP_WAIT(0); }
        __syncthreads();   // chunk c visible
        mma_chunk(smb, c & 1, (c & 1) ? acc_y : acc_x, mwarp, nhalf, lane);
        if (c < 2) {
            __syncthreads();              // all warps done reading buf
            issue_chunk_n(smb, c + 2, I, J, tid);
        }
    }

    // ---- fused epilogue: dx & dy from registers, cross product local ----
    float ssa = 0.f, ssb = 0.f, sab = 0.f;
    float colpa[8][2], colpb[8][2];
    float rowpa[2][2] = {{0.f, 0.f}, {0.f, 0.f}};
    float rowpb[2][2] = {{0.f, 0.f}, {0.f, 0.f}};
#pragma unroll
    for (int nt = 0; nt < 8; nt++) {
        colpa[nt][0] = 0.f; colpa[nt][1] = 0.f;
        colpb[nt][0] = 0.f; colpb[nt][1] = 0.f;
    }

#pragma unroll
    for (int mt = 0; mt < 2; mt++) {
#pragma unroll
        for (int pr = 0; pr < 2; pr++) {
            const int row = mwarp * 32 + mt * 16 + pr * 8 + (lane >> 2);
            const float nIx = NIX[row];
            const float nIy = NIY[row];
#pragma unroll
            for (int nt = 0; nt < 8; nt++) {
                const int col = nhalf * 64 + nt * 8 + (lane & 3) * 2;
                float gx0 = acc_x[mt][nt][pr * 2 + 0];
                float gx1 = acc_x[mt][nt][pr * 2 + 1];
                float gy0 = acc_y[mt][nt][pr * 2 + 0];
                float gy1 = acc_y[mt][nt][pr * 2 + 1];
                float sqx0 = fmaf(-2.f, gx0, nIx + NJX[col]);
                float sqx1 = fmaf(-2.f, gx1, nIx + NJX[col + 1]);
                float sqy0 = fmaf(-2.f, gy0, nIy + NJY[col]);
                float sqy1 = fmaf(-2.f, gy1, nIy + NJY[col + 1]);
                float dx0 = (sqx0 > 0.f) ? sqx0 * rsqrtf(sqx0) : 0.f;
                float dx1 = (sqx1 > 0.f) ? sqx1 * rsqrtf(sqx1) : 0.f;
                float dy0 = (sqy0 > 0.f) ? sqy0 * rsqrtf(sqy0) : 0.f;
                float dy1 = (sqy1 > 0.f) ? sqy1 * rsqrtf(sqy1) : 0.f;
                if (diag) {
                    if (row == col)     { dx0 = 0.f; dy0 = 0.f; }
                    if (row == col + 1) { dx1 = 0.f; dy1 = 0.f; }
                }
                ssa = fmaf(dx0, dx0, ssa); ssa = fmaf(dx1, dx1, ssa);
                ssb = fmaf(dy0, dy0, ssb); ssb = fmaf(dy1, dy1, ssb);
                sab = fmaf(dx0, dy0, sab); sab = fmaf(dx1, dy1, sab);
                rowpa[mt][pr] += dx0 + dx1;
                rowpb[mt][pr] += dy0 + dy1;
                colpa[nt][0] += dx0; colpa[nt][1] += dx1;
                colpb[nt][0] += dy0; colpb[nt][1] += dy1;
            }
        }
    }
    double s_aa = (double)ssa, s_bb = (double)ssb, s_ab = (double)sab;

    // col sums: reduce over the 8 row-lanes (stride-4 lanes)
#pragma unroll
    for (int nt = 0; nt < 8; nt++)
#pragma unroll
        for (int c2 = 0; c2 < 2; c2++) {
            float va = colpa[nt][c2], vb = colpb[nt][c2];
            va += __shfl_down_sync(FULL, va, 16);
            va += __shfl_down_sync(FULL, va, 8);
            va += __shfl_down_sync(FULL, va, 4);
            vb += __shfl_down_sync(FULL, vb, 16);
            vb += __shfl_down_sync(FULL, vb, 8);
            vb += __shfl_down_sync(FULL, vb, 4);
            colpa[nt][c2] = va; colpb[nt][c2] = vb;
        }
    if (lane < 4) {
#pragma unroll
        for (int nt = 0; nt < 8; nt++) {
            const int col = nhalf * 64 + nt * 8 + lane * 2;
            COLPA[mwarp * 128 + col]     = colpa[nt][0];
            COLPA[mwarp * 128 + col + 1] = colpa[nt][1];
            COLPB[mwarp * 128 + col]     = colpb[nt][0];
            COLPB[mwarp * 128 + col + 1] = colpb[nt][1];
        }
    }
    // row sums: reduce over the 4 col-lanes
#pragma unroll
    for (int mt = 0; mt < 2; mt++)
#pragma unroll
        for (int pr = 0; pr < 2; pr++) {
            float va = rowpa[mt][pr], vb = rowpb[mt][pr];
            va += __shfl_down_sync(FULL, va, 1);
            va += __shfl_down_sync(FULL, va, 2);
            vb += __shfl_down_sync(FULL, vb, 1);
            vb += __shfl_down_sync(FULL, vb, 2);
            rowpa[mt][pr] = va; rowpb[mt][pr] = vb;
        }
    if ((lane & 3) == 0) {
#pragma unroll
        for (int mt = 0; mt < 2; mt++)
#pragma unroll
            for (int pr = 0; pr < 2; pr++) {
                const int row = mwarp * 32 + mt * 16 + pr * 8 + (lane >> 2);
                ROWPA[nhalf * 128 + row] = rowpa[mt][pr];
                ROWPB[nhalf * 128 + row] = rowpb[mt][pr];
            }
    }
    __syncthreads();
    if (tid < 128) {
        float csa = COLPA[tid] + COLPA[128 + tid] + COLPA[256 + tid] + COLPA[384 + tid];
        float csb = COLPB[tid] + COLPB[128 + tid] + COLPB[256 + tid] + COLPB[384 + tid];
        float rsa = ROWPA[tid] + ROWPA[128 + tid];
        float rsb = ROWPB[tid] + ROWPB[128 + tid];
        atomicAdd(&g_rs_a[I + tid], (double)rsa);
        atomicAdd(&g_rs_b[I + tid], (double)rsb);
        if (!diag) {
            atomicAdd(&g_rs_a[J + tid], (double)csa);
            atomicAdd(&g_rs_b[J + tid], (double)csb);
        }
    }

    // ---- block scalar reduction ----
    const double w = diag ? 1.0 : 2.0;
    s_aa *= w; s_bb *= w; s_ab *= w;
#pragma unroll
    for (int o = 16; o; o >>= 1) {
        s_aa += __shfl_down_sync(FULL, s_aa, o);
        s_bb += __shfl_down_sync(FULL, s_bb, o);
        s_ab += __shfl_down_sync(FULL, s_ab, o);
    }
    __shared__ double redS[3][8];
    if (lane == 0) { redS[0][warp] = s_aa; redS[1][warp] = s_bb; redS[2][warp] = s_ab; }
    __syncthreads();
    if (tid == 0) {
        double a = 0, b = 0, c = 0;
#pragma unroll
        for (int k = 0; k < 8; k++) { a += redS[0][k]; b += redS[1][k]; c += redS[2][k]; }
        atomicAdd(&g_S[0], a);
        atomicAdd(&g_S[1], b);
        atomicAdd(&g_S[2], c);
    }
}

// ---- kernel 3: combine + final scalar ----
__global__ void finalize_kernel(float* __restrict__ out) {
    int tid = threadIdx.x;
    double dAB = 0, dAA = 0, dBB = 0, Ta = 0, Tb = 0;
    for (int i = tid; i < NPTS; i += 256) {
        double a = g_rs_a[i], b = g_rs_b[i];
        dAB += a * b; dAA += a * a; dBB += b * b; Ta += a; Tb += b;
    }
    const unsigned FULL = 0xffffffffu;
#pragma unroll
    for (int o = 16; o; o >>= 1) {
        dAB += __shfl_down_sync(FULL, dAB, o);
        dAA += __shfl_down_sync(FULL, dAA, o);
        dBB += __shfl_down_sync(FULL, dBB, o);
        Ta  += __shfl_down_sync(FULL, Ta,  o);
        Tb  += __shfl_down_sync(FULL, Tb,  o);
    }
    __shared__ double red[5][8];
    int wid = tid >> 5, lane = tid & 31;
    if (lane == 0) {
        red[0][wid] = dAB; red[1][wid] = dAA; red[2][wid] = dBB;
        red[3][wid] = Ta;  red[4][wid] = Tb;
    }
    __syncthreads();
    if (tid == 0) {
        double sAB = 0, sAA = 0, sBB = 0, ta = 0, tb = 0;
#pragma unroll
        for (int k = 0; k < 8; k++) {
            sAB += red[0][k]; sAA += red[1][k]; sBB += red[2][k];
            ta  += red[3][k]; tb  += red[4][k];
        }
        const double n = (double)NPTS;
        const double inv_n2 = 1.0 / (n * n);
        double xy = (g_S[2] - (2.0 / n) * sAB + ta * tb * inv_n2) * inv_n2;
        double xx = (g_S[0] - (2.0 / n) * sAA + ta * ta * inv_n2) * inv_n2;
        double yy = (g_S[1] - (2.0 / n) * sBB + tb * tb * inv_n2) * inv_n2;
        xy = fmax(xy, 0.0); xx = fmax(xx, 0.0); yy = fmax(yy, 0.0);
        double dcor = -sqrt(xy) / sqrt(sqrt(xx) * sqrt(yy));
        out[0] = (float)dcor;
    }
}

extern "C" void kernel_launch(void* const* d_in, const int* in_sizes, int n_in,
                              void* d_out, int out_size) {
    (void)in_sizes; (void)n_in; (void)out_size;
    const float* x = (const float*)d_in[0];
    const float* y = (const float*)d_in[1];
    float* out = (float*)d_out;

    cudaFuncSetAttribute(dcor_mma_kernel,
                         cudaFuncAttributeMaxDynamicSharedMemorySize, SMEM_BYTES);

    prep_kernel<<<NPTS / 8, 256>>>(x, y);
    dim3 grid(NB, NB);
    dcor_mma_kernel<<<grid, 256, SMEM_BYTES>>>();
    finalize_kernel<<<1, 256>>>(out);
}